// round 15
// baseline (speedup 1.0000x reference)
#include <cuda_runtime.h>
#include <cstdint>
#include <math.h>

// Problem constants (fixed by setup_inputs)
#define WINC    20
#define OFFSETC 40
#define FDIM    8192
#define CDIM    256
#define PDIM    256
#define NBLK    256            // 8 blocks per batch (B=32)  — R10 geometry
#define NTHR    1024

// Gaussian taps g[i] = exp(-0.5*((i-4)/4)^2) / sum, precomputed to float32
// accuracy (matches the jnp float32 computation to ~1e-7 relative).
#define G0 0.08167445f
#define G1 0.10164549f
#define G2 0.11883562f
#define G3 0.13051539f
#define G4 0.13465840f

__device__ float        g_acc    = 0.0f;   // self-resetting accumulator
__device__ unsigned int g_ticket = 0;      // self-resetting arrival counter

__device__ __forceinline__ float block_reduce_sum(float v) {
    __shared__ float sh[32];
    int lane = threadIdx.x & 31;
    int w    = threadIdx.x >> 5;
    #pragma unroll
    for (int o = 16; o; o >>= 1) v += __shfl_down_sync(0xffffffffu, v, o);
    if (lane == 0) sh[w] = v;
    __syncthreads();
    int nw = blockDim.x >> 5;
    v = (threadIdx.x < nw) ? sh[threadIdx.x] : 0.0f;
    if (w == 0) {
        #pragma unroll
        for (int o = 16; o; o >>= 1) v += __shfl_down_sync(0xffffffffu, v, o);
    }
    return v;
}

// Single-wave kernel (R10 geometry, best bench): 256 blocks x 1024 threads.
// Block bid -> batch b = bid>>3, sub-chunk sub = bid&7.
//  each thread: one silence frame;  each warp: one phoneme.
// Tail (single graph node, no memset): relaxed float atomicAdd into g_acc,
// then a ticket atomicAdd made data-dependent on the g_acc return value so
// each block's sum is globally performed before its arrival is visible.
// The last arriver publishes out[0] = atomicExch(g_acc, 0) and resets.
__global__ void __launch_bounds__(NTHR, 2)
fused_kernel(const float* __restrict__ X,
             const int* __restrict__ lengths,
             const int* __restrict__ tgt,
             const int* __restrict__ p_end,
             const int* __restrict__ pnum,
             float* __restrict__ out) {
    const unsigned FULL = 0xffffffffu;
    int bid  = blockIdx.x;
    int tid  = threadIdx.x;
    int lane = tid & 31;
    int wid  = tid >> 5;
    int b    = bid >> 3;
    int sub  = bid & 7;

    // Uniform per-block batch metadata (broadcast loads)
    int len = __ldg(&lengths[b]);
    int pn  = __ldg(&pnum[b]);
    int ends_ph = min(__ldg(&p_end[b]) + OFFSETC, len);
    const float* xp = X + (size_t)b * FDIM * CDIM;

    // ---- phoneme setup: issue tgt load early so tgt->X chain overlaps sil ----
    int p = (sub << 5) + wid;              // warp wid -> phoneme p
    bool ph_act = (p < pn);
    int c = ph_act ? __ldg(&tgt[b * PDIM + p]) : 0;
    int start = max(ends_ph - WINC * (pn - p), 0);
    int wlen  = min(start + WINC, len) - start;

    float contrib = 0.0f;

    // ---------- silence term: one frame per thread ----------
    {
        int first_start = max(ends_ph - WINC * pn, 0);
        int last_end    = min(max(ends_ph - WINC, 0) + WINC, len);
        int tf = (sub << 10) + tid;
        // mask = (tf < first_start) | ((tf >= last_end) & (tf < len))
        if ((tf < first_start) || ((tf >= last_end) && (tf < len))) {
            contrib = -__ldcg(&xp[(size_t)tf * CDIM]);   // SIL column = 0
        }
    }

    // ---------- phoneme term: one (b, p) per warp ----------
    if (ph_act) {
        float v = 0.0f;
        if (lane < WINC && lane < wlen) {
            int fi = min(start + lane, FDIM - 1);
            v = __ldcg(&xp[(size_t)fi * CDIM + c]);
        }

        // smoothed[lane] = sum_i g[i] * v[lane + i - 3]; out-of-range -> 0
        // (idx & 31 wraps onto lanes >= 20 which hold v = 0)
        float v0 = __shfl_sync(FULL, v, (lane - 3) & 31);
        float v1 = __shfl_sync(FULL, v, (lane - 2) & 31);
        float v2 = __shfl_sync(FULL, v, (lane - 1) & 31);
        float v4 = __shfl_sync(FULL, v, (lane + 1) & 31);
        float v5 = __shfl_sync(FULL, v, (lane + 2) & 31);
        float v6 = __shfl_sync(FULL, v, (lane + 3) & 31);
        float v7 = __shfl_sync(FULL, v, (lane + 4) & 31);
        float v8 = __shfl_sync(FULL, v, (lane + 5) & 31);
        float sm = G0 * v0;
        sm = fmaf(G1, v1, sm);
        sm = fmaf(G2, v2, sm);
        sm = fmaf(G3, v,  sm);
        sm = fmaf(G4, v4, sm);
        sm = fmaf(G3, v5, sm);
        sm = fmaf(G2, v6, sm);
        sm = fmaf(G1, v7, sm);
        sm = fmaf(G0, v8, sm);

        float m = (lane < wlen && lane < WINC) ? sm : -INFINITY;
        #pragma unroll
        for (int o = 16; o; o >>= 1) m = fmaxf(m, __shfl_xor_sync(FULL, m, o));
        if (lane == 0) contrib += -m;
    }

    float tot = block_reduce_sum(contrib);

    if (tid == 0) {
        // 1) add our partial into the device accumulator (performed at L2)
        float old = atomicAdd(&g_acc, tot);
        // 2) ticket increment, data-dependent on the returned value:
        //    the predicate below is always true (finite partial sums can never
        //    produce this NaN payload), but the compiler cannot prove it, so
        //    the ticket atomic waits for the g_acc atomic's completion.
        if (__float_as_uint(old) != 0x7f800001u) {
            unsigned int t = atomicAdd(&g_ticket, 1u);
            if (t == (unsigned int)(NBLK - 1)) {
                // publish and re-zero in one L2 atomic (all adds serialized
                // at this address before our exchange)
                out[0] = atomicExch(&g_acc, 0.0f);
                g_ticket = 0;      // plain store; visible by next launch
            }
        }
    }
}

extern "C" void kernel_launch(void* const* d_in, const int* in_sizes, int n_in,
                              void* d_out, int out_size) {
    const float* X       = (const float*)d_in[0];
    const int*   lengths = (const int*)d_in[1];
    const int*   tgt     = (const int*)d_in[2];
    const int*   p_end   = (const int*)d_in[3];
    const int*   pnum    = (const int*)d_in[4];
    float*       out     = (float*)d_out;

    fused_kernel<<<NBLK, NTHR>>>(X, lengths, tgt, p_end, pnum, out);
}

// round 16
// speedup vs baseline: 1.0485x; 1.0485x over previous
#include <cuda_runtime.h>
#include <cstdint>
#include <math.h>

// Problem constants (fixed by setup_inputs)
#define WINC    20
#define OFFSETC 40
#define FDIM    8192
#define CDIM    256
#define PDIM    256
#define NBLK    256            // 8 blocks per batch (B=32)
#define NTHR    1024

// Gaussian taps g[i] = exp(-0.5*((i-4)/4)^2) / sum, precomputed to float32
// accuracy (matches the jnp float32 computation to ~1e-7 relative).
__device__ __constant__ const float G0 = 0.08167445f;
__device__ __constant__ const float G1 = 0.10164549f;
__device__ __constant__ const float G2 = 0.11883562f;
__device__ __constant__ const float G3 = 0.13051539f;
__device__ __constant__ const float G4 = 0.13465840f;

__device__ __forceinline__ float block_reduce_sum(float v) {
    __shared__ float sh[32];
    int lane = threadIdx.x & 31;
    int w    = threadIdx.x >> 5;
    #pragma unroll
    for (int o = 16; o; o >>= 1) v += __shfl_down_sync(0xffffffffu, v, o);
    if (lane == 0) sh[w] = v;
    __syncthreads();
    int nw = blockDim.x >> 5;
    v = (threadIdx.x < nw) ? sh[threadIdx.x] : 0.0f;
    if (w == 0) {
        #pragma unroll
        for (int o = 16; o; o >>= 1) v += __shfl_down_sync(0xffffffffu, v, o);
    }
    return v;
}

// Single-wave kernel: 256 blocks x 1024 threads (2 blocks/SM).
// Block bid -> batch b = bid>>3, sub-chunk sub = bid&7.
//  each thread: one silence frame;  each warp: one phoneme.
// Block partial -> RED.ADD.F32 into out[0] (all terms >= 0; reorder error ~1e-7).
__global__ void __launch_bounds__(NTHR, 2)
fused_kernel(const float* __restrict__ X,
             const int* __restrict__ lengths,
             const int* __restrict__ tgt,
             const int* __restrict__ p_end,
             const int* __restrict__ pnum,
             float* __restrict__ out) {
    const unsigned FULL = 0xffffffffu;
    int bid  = blockIdx.x;
    int tid  = threadIdx.x;
    int lane = tid & 31;
    int wid  = tid >> 5;
    int b    = bid >> 3;
    int sub  = bid & 7;

    // Uniform per-block batch metadata (broadcast loads)
    int len = __ldg(&lengths[b]);
    int pn  = __ldg(&pnum[b]);
    int ends_ph = min(__ldg(&p_end[b]) + OFFSETC, len);
    const float* xp = X + (size_t)b * FDIM * CDIM;

    // ---- phoneme setup: issue tgt load early so tgt->X chain overlaps sil ----
    int p = (sub << 5) + wid;              // warp wid -> phoneme p
    bool ph_act = (p < pn);
    int c = ph_act ? __ldg(&tgt[b * PDIM + p]) : 0;
    int start = max(ends_ph - WINC * (pn - p), 0);
    int wlen  = min(start + WINC, len) - start;

    float contrib = 0.0f;

    // ---------- silence term: one frame per thread ----------
    {
        int first_start = max(ends_ph - WINC * pn, 0);
        int last_end    = min(max(ends_ph - WINC, 0) + WINC, len);
        int tf = (sub << 10) + tid;
        // mask = (tf < first_start) | ((tf >= last_end) & (tf < len))
        if ((tf < first_start) || ((tf >= last_end) && (tf < len))) {
            contrib = -xp[(size_t)tf * CDIM];      // SIL column = 0
        }
    }

    // ---------- phoneme term: one (b, p) per warp ----------
    if (ph_act) {
        float v = 0.0f;
        if (lane < WINC && lane < wlen) {
            int fi = min(start + lane, FDIM - 1);
            v = xp[(size_t)fi * CDIM + c];
        }

        // smoothed[lane] = sum_i g[i] * v[lane + i - 3]; out-of-range -> 0
        // (idx & 31 wraps onto lanes >= 20 which hold v = 0)
        float sm;
        {
            float v0 = __shfl_sync(FULL, v, (lane - 3) & 31);
            float v1 = __shfl_sync(FULL, v, (lane - 2) & 31);
            float v2 = __shfl_sync(FULL, v, (lane - 1) & 31);
            float v3 = v;
            float v4 = __shfl_sync(FULL, v, (lane + 1) & 31);
            float v5 = __shfl_sync(FULL, v, (lane + 2) & 31);
            float v6 = __shfl_sync(FULL, v, (lane + 3) & 31);
            float v7 = __shfl_sync(FULL, v, (lane + 4) & 31);
            float v8 = __shfl_sync(FULL, v, (lane + 5) & 31);
            sm = G0 * v0;
            sm = fmaf(G1, v1, sm);
            sm = fmaf(G2, v2, sm);
            sm = fmaf(G3, v3, sm);
            sm = fmaf(G4, v4, sm);
            sm = fmaf(G3, v5, sm);
            sm = fmaf(G2, v6, sm);
            sm = fmaf(G1, v7, sm);
            sm = fmaf(G0, v8, sm);
        }

        float m = (lane < wlen && lane < WINC) ? sm : -INFINITY;
        #pragma unroll
        for (int o = 16; o; o >>= 1) m = fmaxf(m, __shfl_xor_sync(FULL, m, o));
        if (lane == 0) contrib += -m;
    }

    float tot = block_reduce_sum(contrib);
    if (tid == 0) atomicAdd(out, tot);     // RED.ADD.F32, no-return fast path
}

extern "C" void kernel_launch(void* const* d_in, const int* in_sizes, int n_in,
                              void* d_out, int out_size) {
    const float* X       = (const float*)d_in[0];
    const int*   lengths = (const int*)d_in[1];
    const int*   tgt     = (const int*)d_in[2];
    const int*   p_end   = (const int*)d_in[3];
    const int*   pnum    = (const int*)d_in[4];
    float*       out     = (float*)d_out;

    cudaMemsetAsync(out, 0, sizeof(float));          // graph-capturable memset node
    fused_kernel<<<NBLK, NTHR>>>(X, lengths, tgt, p_end, pnum, out);
}